// round 1
// baseline (speedup 1.0000x reference)
#include <cuda_runtime.h>
#include <cuda_fp16.h>
#include <stdint.h>

#define B_   32
#define T_   2048
#define D_   256
#define H_   256
#define G_   1024   // 4*H

// Scratch: permuted input-gate preactivations [B,T,1024] fp32 (includes both biases)
__device__ float g_xg[(size_t)B_ * T_ * G_];
__device__ float g_bias[G_];

// Column permutation used everywhere:
//   stored col n = r*256 + g*64 + jj  <->  original gate row = g*256 + r*64 + jj
// so that phase-2 CTA (batch b, rank r) reads 256 contiguous floats per step.

// ---------------------------------------------------------------------------
// bias permute
// ---------------------------------------------------------------------------
__global__ void bias_kernel(const float* __restrict__ b_ih,
                            const float* __restrict__ b_hh) {
    int n = blockIdx.x * blockDim.x + threadIdx.x;
    if (n < G_) {
        int r = n >> 8, rem = n & 255, g = rem >> 6, jj = rem & 63;
        int orig = g * 256 + r * 64 + jj;
        g_bias[n] = b_ih[orig] + b_hh[orig];
    }
}

// ---------------------------------------------------------------------------
// Phase 1: xg[m][n] = sum_k relu(x[m][k]) * W_ih[orig(n)][k] + bias[n]
// fp16 mma.sync m16n8k16, fp32 accumulate. CTA tile 128x128, K=256 one-shot.
// ---------------------------------------------------------------------------
#define ASTRIDE 264   // halves per smem row (4-bank shift per row -> conflict free)

__global__ __launch_bounds__(256) void gemm_kernel(const float* __restrict__ x,
                                                   const float* __restrict__ w_ih) {
    extern __shared__ half sm[];
    half* As = sm;                    // [128][ASTRIDE]
    half* Bs = sm + 128 * ASTRIDE;    // [128][ASTRIDE]

    int tid = threadIdx.x;
    int n0 = blockIdx.x * 128;
    int m0 = blockIdx.y * 128;

    // Load A tile: relu(x) -> fp16
    for (int i = tid; i < 128 * 64; i += 256) {
        int row = i >> 6, c4 = i & 63;
        float4 v = *(const float4*)(x + (size_t)(m0 + row) * 256 + c4 * 4);
        v.x = fmaxf(v.x, 0.f); v.y = fmaxf(v.y, 0.f);
        v.z = fmaxf(v.z, 0.f); v.w = fmaxf(v.w, 0.f);
        *(half2*)(As + row * ASTRIDE + c4 * 4)     = __floats2half2_rn(v.x, v.y);
        *(half2*)(As + row * ASTRIDE + c4 * 4 + 2) = __floats2half2_rn(v.z, v.w);
    }
    // Load B tile: permuted W_ih rows -> fp16
    for (int i = tid; i < 128 * 64; i += 256) {
        int row = i >> 6, c4 = i & 63;
        int ng = n0 + row;
        int r = ng >> 8, rem = ng & 255, g = rem >> 6, jj = rem & 63;
        int orig = g * 256 + r * 64 + jj;
        float4 v = *(const float4*)(w_ih + (size_t)orig * 256 + c4 * 4);
        *(half2*)(Bs + row * ASTRIDE + c4 * 4)     = __floats2half2_rn(v.x, v.y);
        *(half2*)(Bs + row * ASTRIDE + c4 * 4 + 2) = __floats2half2_rn(v.z, v.w);
    }
    __syncthreads();

    int lane = tid & 31, warp = tid >> 5;
    int wm = warp & 3;     // 4 warps over M (32 rows each)
    int wn = warp >> 2;    // 2 warps over N (64 cols each)
    int gr = lane >> 2;    // 0..7
    int qc = (lane & 3) * 2;

    float acc[2][8][4];
    #pragma unroll
    for (int a = 0; a < 2; a++)
        #pragma unroll
        for (int b = 0; b < 8; b++)
            #pragma unroll
            for (int c = 0; c < 4; c++) acc[a][b][c] = 0.f;

    #pragma unroll
    for (int k0 = 0; k0 < 256; k0 += 16) {
        uint32_t af[2][4];
        #pragma unroll
        for (int mt = 0; mt < 2; mt++) {
            int rb = wm * 32 + mt * 16 + gr;
            af[mt][0] = *(const uint32_t*)(As + rb * ASTRIDE + k0 + qc);
            af[mt][1] = *(const uint32_t*)(As + (rb + 8) * ASTRIDE + k0 + qc);
            af[mt][2] = *(const uint32_t*)(As + rb * ASTRIDE + k0 + qc + 8);
            af[mt][3] = *(const uint32_t*)(As + (rb + 8) * ASTRIDE + k0 + qc + 8);
        }
        #pragma unroll
        for (int nt = 0; nt < 8; nt++) {
            int nr = wn * 64 + nt * 8 + gr;
            uint32_t b0 = *(const uint32_t*)(Bs + nr * ASTRIDE + k0 + qc);
            uint32_t b1 = *(const uint32_t*)(Bs + nr * ASTRIDE + k0 + qc + 8);
            #pragma unroll
            for (int mt = 0; mt < 2; mt++) {
                asm volatile(
                    "mma.sync.aligned.m16n8k16.row.col.f32.f16.f16.f32 "
                    "{%0,%1,%2,%3}, {%4,%5,%6,%7}, {%8,%9}, {%0,%1,%2,%3};\n"
                    : "+f"(acc[mt][nt][0]), "+f"(acc[mt][nt][1]),
                      "+f"(acc[mt][nt][2]), "+f"(acc[mt][nt][3])
                    : "r"(af[mt][0]), "r"(af[mt][1]), "r"(af[mt][2]), "r"(af[mt][3]),
                      "r"(b0), "r"(b1));
            }
        }
    }

    #pragma unroll
    for (int mt = 0; mt < 2; mt++) {
        #pragma unroll
        for (int nt = 0; nt < 8; nt++) {
            int col = n0 + wn * 64 + nt * 8 + qc;
            float bv0 = g_bias[col], bv1 = g_bias[col + 1];
            int row = m0 + wm * 32 + mt * 16 + gr;
            float2 v0 = {acc[mt][nt][0] + bv0, acc[mt][nt][1] + bv1};
            float2 v1 = {acc[mt][nt][2] + bv0, acc[mt][nt][3] + bv1};
            *(float2*)(g_xg + (size_t)row * G_ + col)       = v0;
            *(float2*)(g_xg + (size_t)(row + 8) * G_ + col) = v1;
        }
    }
}

// ---------------------------------------------------------------------------
// Phase 2: persistent LSTM scan. One 4-CTA cluster per batch element.
// Thread t of CTA rank r owns permuted gate row (t/64)*256 + r*64 + (t%64)
// as 128 half2 registers. Per step: 128 HFMA2 into 8 fp16x2 chains,
// fp32 combine + xg, activations via ex2/rcp, h broadcast via DSMEM.
// ---------------------------------------------------------------------------
__device__ __forceinline__ uint32_t smem_u32(const void* p) {
    return (uint32_t)__cvta_generic_to_shared(p);
}

__global__ __launch_bounds__(256, 1) __cluster_dims__(4, 1, 1)
void lstm_kernel(const float* __restrict__ w_hh, float* __restrict__ out) {
    __shared__ __align__(16) half hbuf[2][256];   // double-buffered h (fp16)
    __shared__ __align__(16) half stage[64];      // this CTA's new h slice
    __shared__ float act[256];                    // activated gates
    __shared__ __align__(8) unsigned long long mbar;

    int tid = threadIdx.x;
    int b = blockIdx.x >> 2;
    int r = blockIdx.x & 3;
    int q = tid >> 6;        // gate quadrant 0..3 (i,f,g,o)
    int jj = tid & 63;       // h index within this CTA's slice

    // --- load this thread's weight row into registers as fp16 pairs ---
    int orig = q * 256 + r * 64 + jj;
    const float4* wr = (const float4*)(w_hh + (size_t)orig * 256);
    half2 w2[128];
    #pragma unroll
    for (int i = 0; i < 64; i++) {
        float4 v = wr[i];
        w2[2 * i]     = __floats2half2_rn(v.x, v.y);
        w2[2 * i + 1] = __floats2half2_rn(v.z, v.w);
    }

    // --- init smem ---
    ((uint32_t*)hbuf)[tid] = 0u;   // 256 u32 = both h buffers zeroed
    if (tid == 0) {
        uint32_t cnt = 32;
        asm volatile("mbarrier.init.shared.b64 [%0], %1;"
                     :: "r"(smem_u32(&mbar)), "r"(cnt) : "memory");
    }
    __syncthreads();
    asm volatile("barrier.cluster.arrive.aligned;" ::: "memory");
    asm volatile("barrier.cluster.wait.aligned;" ::: "memory");

    // --- precompute remote DSMEM addresses for the broadcast threads ---
    uint32_t raddr0 = 0, raddr1 = 0, rmbar = 0;
    if (tid < 32) {
        uint32_t trg = tid >> 3;            // target cluster rank
        uint32_t ch = tid & 7;              // 16B chunk within 128B slice
        uint32_t l0 = smem_u32(&hbuf[0][0]) + (uint32_t)r * 128 + ch * 16;
        uint32_t l1 = smem_u32(&hbuf[1][0]) + (uint32_t)r * 128 + ch * 16;
        uint32_t lm = smem_u32(&mbar);
        asm("mapa.shared::cluster.u32 %0, %1, %2;" : "=r"(raddr0) : "r"(l0), "r"(trg));
        asm("mapa.shared::cluster.u32 %0, %1, %2;" : "=r"(raddr1) : "r"(l1), "r"(trg));
        asm("mapa.shared::cluster.u32 %0, %1, %2;" : "=r"(rmbar)  : "r"(lm), "r"(trg));
    }

    float c = 0.f;
    size_t xgbase = (size_t)b * T_ * G_ + (size_t)r * 256 + tid;
    size_t obase = (size_t)b * T_ * H_ + (size_t)r * 64 + jj;
    const uint32_t mb = smem_u32(&mbar);

    float xg_cur = g_xg[xgbase];
    float xg_nx  = g_xg[xgbase + G_];

    for (int t = 0; t < T_; t++) {
        if (t > 0) {
            uint32_t par = (t - 1) & 1;
            asm volatile(
                "{\n\t.reg .pred p;\n"
                "LW%=:\n\t"
                "mbarrier.try_wait.parity.acquire.cluster.shared::cta.b64 p, [%0], %1;\n\t"
                "@!p bra LW%=;\n\t}"
                :: "r"(mb), "r"(par) : "memory");
        }

        // prefetch xg two steps ahead
        float xg_n2 = 0.f;
        if (t + 2 < T_) xg_n2 = __ldg(&g_xg[xgbase + (size_t)(t + 2) * G_]);

        // --- dot product: 8 independent fp16x2 accumulation chains ---
        const uint4* hv = (const uint4*)hbuf[t & 1];
        half2 a[8];
        #pragma unroll
        for (int i = 0; i < 8; i++) a[i] = __floats2half2_rn(0.f, 0.f);
        #pragma unroll
        for (int kk = 0; kk < 32; kk++) {
            uint4 h4 = hv[kk];   // broadcast LDS.128: 8 halves of h
            a[(4 * kk + 0) & 7] = __hfma2(w2[4 * kk + 0], *(half2*)&h4.x, a[(4 * kk + 0) & 7]);
            a[(4 * kk + 1) & 7] = __hfma2(w2[4 * kk + 1], *(half2*)&h4.y, a[(4 * kk + 1) & 7]);
            a[(4 * kk + 2) & 7] = __hfma2(w2[4 * kk + 2], *(half2*)&h4.z, a[(4 * kk + 2) & 7]);
            a[(4 * kk + 3) & 7] = __hfma2(w2[4 * kk + 3], *(half2*)&h4.w, a[(4 * kk + 3) & 7]);
        }
        float s = 0.f;
        #pragma unroll
        for (int i = 0; i < 8; i++) {
            float2 fv = __half22float2(a[i]);
            s += fv.x + fv.y;
        }
        float pre = s + xg_cur;

        // --- activation (q==2 -> tanh, else sigmoid), via ex2 + fast div ---
        float av;
        if (q == 2) {
            float e = __expf(pre + pre);
            av = 1.f - __fdividef(2.f, e + 1.f);
        } else {
            av = __fdividef(1.f, 1.f + __expf(-pre));
        }
        act[tid] = av;
        __syncthreads();

        // --- c/h update by threads 0..63 ---
        if (tid < 64) {
            float gi = act[jj], gf = act[64 + jj], gg = act[128 + jj], go = act[192 + jj];
            c = gf * c + gi * gg;
            float e = __expf(c + c);
            float th = 1.f - __fdividef(2.f, e + 1.f);
            float h = go * th;
            out[obase + (size_t)t * H_] = h;          // exact fp32 h to output
            stage[jj] = __float2half_rn(h);           // fp16 h for the recurrence
        }
        __syncthreads();

        // --- broadcast new h slice to all 4 CTAs' next buffer ---
        if (t < T_ - 1 && tid < 32) {
            uint32_t dst = ((t & 1) == 0) ? raddr1 : raddr0;  // buffer (t+1)&1
            uint4 v = ((const uint4*)stage)[tid & 7];
            asm volatile("st.shared::cluster.u32 [%0],    %1;" :: "r"(dst), "r"(v.x) : "memory");
            asm volatile("st.shared::cluster.u32 [%0+4],  %1;" :: "r"(dst), "r"(v.y) : "memory");
            asm volatile("st.shared::cluster.u32 [%0+8],  %1;" :: "r"(dst), "r"(v.z) : "memory");
            asm volatile("st.shared::cluster.u32 [%0+12], %1;" :: "r"(dst), "r"(v.w) : "memory");
            asm volatile("mbarrier.arrive.release.cluster.shared::cluster.b64 _, [%0];"
                         :: "r"(rmbar) : "memory");
        }

        xg_cur = xg_nx;
        xg_nx = xg_n2;
    }

    asm volatile("barrier.cluster.arrive.aligned;" ::: "memory");
    asm volatile("barrier.cluster.wait.aligned;" ::: "memory");
}

// ---------------------------------------------------------------------------
extern "C" void kernel_launch(void* const* d_in, const int* in_sizes, int n_in,
                              void* d_out, int out_size) {
    const float* x    = (const float*)d_in[0];
    const float* w_ih = (const float*)d_in[1];
    const float* w_hh = (const float*)d_in[2];
    const float* b_ih = (const float*)d_in[3];
    const float* b_hh = (const float*)d_in[4];
    float* out = (float*)d_out;

    bias_kernel<<<4, 256>>>(b_ih, b_hh);

    const int smem = 2 * 128 * ASTRIDE * (int)sizeof(half);  // 135168
    cudaFuncSetAttribute(gemm_kernel, cudaFuncAttributeMaxDynamicSharedMemorySize, smem);
    gemm_kernel<<<dim3(8, 512), 256, smem>>>(x, w_ih);

    lstm_kernel<<<128, 256>>>(w_hh, out);
}

// round 3
// speedup vs baseline: 1.0551x; 1.0551x over previous
#include <cuda_runtime.h>
#include <cuda_fp16.h>
#include <stdint.h>

#define B_   32
#define T_   2048
#define D_   256
#define H_   256
#define G_   1024   // 4*H

// Scratch: permuted input-gate preactivations [B,T,1024] fp32 (includes both biases)
__device__ float g_xg[(size_t)B_ * T_ * G_];
__device__ float g_bias[G_];

// Column permutation used everywhere:
//   stored col n = r*256 + g*64 + jj  <->  original gate row = g*256 + r*64 + jj
// so that phase-2 CTA (batch b, rank r) reads 256 contiguous floats per step.

// ---------------------------------------------------------------------------
// bias permute
// ---------------------------------------------------------------------------
__global__ void bias_kernel(const float* __restrict__ b_ih,
                            const float* __restrict__ b_hh) {
    int n = blockIdx.x * blockDim.x + threadIdx.x;
    if (n < G_) {
        int r = n >> 8, rem = n & 255, g = rem >> 6, jj = rem & 63;
        int orig = g * 256 + r * 64 + jj;
        g_bias[n] = b_ih[orig] + b_hh[orig];
    }
}

// ---------------------------------------------------------------------------
// Phase 1: xg[m][n] = sum_k relu(x[m][k]) * W_ih[orig(n)][k] + bias[n]
// fp16 mma.sync m16n8k16, fp32 accumulate. CTA tile 128x128, K=256 one-shot.
// ---------------------------------------------------------------------------
#define ASTRIDE 264   // halves per smem row (4-bank shift per row -> conflict free)

__global__ __launch_bounds__(256) void gemm_kernel(const float* __restrict__ x,
                                                   const float* __restrict__ w_ih) {
    extern __shared__ half sm[];
    half* As = sm;                    // [128][ASTRIDE]
    half* Bs = sm + 128 * ASTRIDE;    // [128][ASTRIDE]

    int tid = threadIdx.x;
    int n0 = blockIdx.x * 128;
    int m0 = blockIdx.y * 128;

    // Load A tile: relu(x) -> fp16
    for (int i = tid; i < 128 * 64; i += 256) {
        int row = i >> 6, c4 = i & 63;
        float4 v = *(const float4*)(x + (size_t)(m0 + row) * 256 + c4 * 4);
        v.x = fmaxf(v.x, 0.f); v.y = fmaxf(v.y, 0.f);
        v.z = fmaxf(v.z, 0.f); v.w = fmaxf(v.w, 0.f);
        *(half2*)(As + row * ASTRIDE + c4 * 4)     = __floats2half2_rn(v.x, v.y);
        *(half2*)(As + row * ASTRIDE + c4 * 4 + 2) = __floats2half2_rn(v.z, v.w);
    }
    // Load B tile: permuted W_ih rows -> fp16
    for (int i = tid; i < 128 * 64; i += 256) {
        int row = i >> 6, c4 = i & 63;
        int ng = n0 + row;
        int r = ng >> 8, rem = ng & 255, g = rem >> 6, jj = rem & 63;
        int orig = g * 256 + r * 64 + jj;
        float4 v = *(const float4*)(w_ih + (size_t)orig * 256 + c4 * 4);
        *(half2*)(Bs + row * ASTRIDE + c4 * 4)     = __floats2half2_rn(v.x, v.y);
        *(half2*)(Bs + row * ASTRIDE + c4 * 4 + 2) = __floats2half2_rn(v.z, v.w);
    }
    __syncthreads();

    int lane = tid & 31, warp = tid >> 5;
    int wm = warp & 3;     // 4 warps over M (32 rows each)
    int wn = warp >> 2;    // 2 warps over N (64 cols each)
    int gr = lane >> 2;    // 0..7
    int qc = (lane & 3) * 2;

    float acc[2][8][4];
    #pragma unroll
    for (int a = 0; a < 2; a++)
        #pragma unroll
        for (int b = 0; b < 8; b++)
            #pragma unroll
            for (int c = 0; c < 4; c++) acc[a][b][c] = 0.f;

    #pragma unroll
    for (int k0 = 0; k0 < 256; k0 += 16) {
        uint32_t af[2][4];
        #pragma unroll
        for (int mt = 0; mt < 2; mt++) {
            int rb = wm * 32 + mt * 16 + gr;
            af[mt][0] = *(const uint32_t*)(As + rb * ASTRIDE + k0 + qc);
            af[mt][1] = *(const uint32_t*)(As + (rb + 8) * ASTRIDE + k0 + qc);
            af[mt][2] = *(const uint32_t*)(As + rb * ASTRIDE + k0 + qc + 8);
            af[mt][3] = *(const uint32_t*)(As + (rb + 8) * ASTRIDE + k0 + qc + 8);
        }
        #pragma unroll
        for (int nt = 0; nt < 8; nt++) {
            int nr = wn * 64 + nt * 8 + gr;
            uint32_t b0 = *(const uint32_t*)(Bs + nr * ASTRIDE + k0 + qc);
            uint32_t b1 = *(const uint32_t*)(Bs + nr * ASTRIDE + k0 + qc + 8);
            #pragma unroll
            for (int mt = 0; mt < 2; mt++) {
                asm volatile(
                    "mma.sync.aligned.m16n8k16.row.col.f32.f16.f16.f32 "
                    "{%0,%1,%2,%3}, {%4,%5,%6,%7}, {%8,%9}, {%0,%1,%2,%3};\n"
                    : "+f"(acc[mt][nt][0]), "+f"(acc[mt][nt][1]),
                      "+f"(acc[mt][nt][2]), "+f"(acc[mt][nt][3])
                    : "r"(af[mt][0]), "r"(af[mt][1]), "r"(af[mt][2]), "r"(af[mt][3]),
                      "r"(b0), "r"(b1));
            }
        }
    }

    #pragma unroll
    for (int mt = 0; mt < 2; mt++) {
        #pragma unroll
        for (int nt = 0; nt < 8; nt++) {
            int col = n0 + wn * 64 + nt * 8 + qc;
            float bv0 = g_bias[col], bv1 = g_bias[col + 1];
            int row = m0 + wm * 32 + mt * 16 + gr;
            float2 v0 = {acc[mt][nt][0] + bv0, acc[mt][nt][1] + bv1};
            float2 v1 = {acc[mt][nt][2] + bv0, acc[mt][nt][3] + bv1};
            *(float2*)(g_xg + (size_t)row * G_ + col)       = v0;
            *(float2*)(g_xg + (size_t)(row + 8) * G_ + col) = v1;
        }
    }
}

// ---------------------------------------------------------------------------
// Phase 2: persistent LSTM scan. One 4-CTA cluster per batch element.
// Thread (q,jj) of CTA rank r owns gate row q*256 + r*64 + jj, weights held
// as 128 half2 registers ROTATED so that k-chunk [64r, 64r+64) is indices
// 0..31 (own-slice-first). Per step:
//   own-chunk FMA -> mbarrier wait -> remote-chunk FMA -> act -> sync ->
//   replicated c/h update in ALL threads -> q0 local store / q1..3 direct
//   per-thread DSMEM u16 send + arrive -> sync.
// ---------------------------------------------------------------------------
__device__ __forceinline__ uint32_t smem_u32(const void* p) {
    return (uint32_t)__cvta_generic_to_shared(p);
}

__global__ __launch_bounds__(256, 1) __cluster_dims__(4, 1, 1)
void lstm_kernel(const float* __restrict__ w_hh, float* __restrict__ out) {
    __shared__ __align__(16) half hbuf[2][256];   // double-buffered h (fp16)
    __shared__ float act[256];                    // activated gates
    __shared__ __align__(8) unsigned long long mbar;

    int tid = threadIdx.x;
    int b = blockIdx.x >> 2;
    int r = blockIdx.x & 3;
    int q = tid >> 6;        // gate quadrant 0..3 (i,f,g,o)
    int jj = tid & 63;       // h index within this CTA's slice

    // --- load this thread's weight row (rotated by own slice) into regs ---
    int orig = q * 256 + r * 64 + jj;
    const float4* wr = (const float4*)(w_hh + (size_t)orig * 256);
    half2 w2[128];
    #pragma unroll
    for (int i = 0; i < 64; i++) {
        float4 v = wr[(16 * r + i) & 63];   // rotation: w2[2i] covers h[(64r+4i)%256..]
        w2[2 * i]     = __floats2half2_rn(v.x, v.y);
        w2[2 * i + 1] = __floats2half2_rn(v.z, v.w);
    }

    // --- init smem ---
    ((uint32_t*)hbuf)[tid] = 0u;   // 256 u32 = both h buffers zeroed
    if (tid == 0) {
        uint32_t cnt = 192;        // 3 peers x 64 threads per step
        asm volatile("mbarrier.init.shared.b64 [%0], %1;"
                     :: "r"(smem_u32(&mbar)), "r"(cnt) : "memory");
    }
    __syncthreads();
    asm volatile("barrier.cluster.arrive.aligned;" ::: "memory");
    asm volatile("barrier.cluster.wait.aligned;" ::: "memory");

    // --- precompute remote DSMEM addresses (q>=1 threads send to peer (r+q)&3) ---
    uint32_t raddr0 = 0, raddr1 = 0, rmbar = 0;
    if (q >= 1) {
        uint32_t trg = (uint32_t)((r + q) & 3);
        uint32_t off = (uint32_t)r * 128 + (uint32_t)jj * 2;  // our slice in peer buf
        uint32_t l0 = smem_u32(&hbuf[0][0]) + off;
        uint32_t l1 = smem_u32(&hbuf[1][0]) + off;
        uint32_t lm = smem_u32(&mbar);
        asm("mapa.shared::cluster.u32 %0, %1, %2;" : "=r"(raddr0) : "r"(l0), "r"(trg));
        asm("mapa.shared::cluster.u32 %0, %1, %2;" : "=r"(raddr1) : "r"(l1), "r"(trg));
        asm("mapa.shared::cluster.u32 %0, %1, %2;" : "=r"(rmbar)  : "r"(lm), "r"(trg));
    }

    float c = 0.f;
    size_t xgbase = (size_t)b * T_ * G_ + (size_t)r * 256 + tid;
    size_t obase = (size_t)b * T_ * H_ + (size_t)r * 64 + jj;
    const uint32_t mb = smem_u32(&mbar);
    const int ubase = 8 * r;   // own-slice uint4 base index in hbuf

    float xg_cur = g_xg[xgbase];
    float xg_nx  = g_xg[xgbase + G_];

    for (int t = 0; t < T_; t++) {
        // prefetch xg two steps ahead (independent, overlaps wait)
        float xg_n2 = 0.f;
        if (t + 2 < T_) xg_n2 = __ldg(&g_xg[xgbase + (size_t)(t + 2) * G_]);

        const uint4* hv = (const uint4*)hbuf[t & 1];
        half2 a[8];
        #pragma unroll
        for (int i = 0; i < 8; i++) a[i] = __floats2half2_rn(0.f, 0.f);

        // --- own-slice chunk first: no cluster wait needed ---
        #pragma unroll
        for (int u = 0; u < 8; u++) {
            uint4 h4 = hv[(ubase + u) & 31];
            int j = 4 * u;
            a[(j + 0) & 7] = __hfma2(w2[j + 0], *(half2*)&h4.x, a[(j + 0) & 7]);
            a[(j + 1) & 7] = __hfma2(w2[j + 1], *(half2*)&h4.y, a[(j + 1) & 7]);
            a[(j + 2) & 7] = __hfma2(w2[j + 2], *(half2*)&h4.z, a[(j + 2) & 7]);
            a[(j + 3) & 7] = __hfma2(w2[j + 3], *(half2*)&h4.w, a[(j + 3) & 7]);
        }

        // --- wait for remote slices (sent at end of step t-1) ---
        if (t > 0) {
            uint32_t par = (t - 1) & 1;
            asm volatile(
                "{\n\t.reg .pred p;\n"
                "LW%=:\n\t"
                "mbarrier.try_wait.parity.acquire.cluster.shared::cta.b64 p, [%0], %1, 0x989680;\n\t"
                "@!p bra LW%=;\n\t}"
                :: "r"(mb), "r"(par) : "memory");
        }

        // --- remote chunks ---
        #pragma unroll
        for (int u = 8; u < 32; u++) {
            uint4 h4 = hv[(ubase + u) & 31];
            int j = 4 * u;
            a[(j + 0) & 7] = __hfma2(w2[j + 0], *(half2*)&h4.x, a[(j + 0) & 7]);
            a[(j + 1) & 7] = __hfma2(w2[j + 1], *(half2*)&h4.y, a[(j + 1) & 7]);
            a[(j + 2) & 7] = __hfma2(w2[j + 2], *(half2*)&h4.z, a[(j + 2) & 7]);
            a[(j + 3) & 7] = __hfma2(w2[j + 3], *(half2*)&h4.w, a[(j + 3) & 7]);
        }

        float s = 0.f;
        #pragma unroll
        for (int i = 0; i < 8; i++) {
            float2 fv = __half22float2(a[i]);
            s += fv.x + fv.y;
        }
        float pre = s + xg_cur;

        // --- activation (q==2 -> tanh, else sigmoid) ---
        float av;
        if (q == 2) {
            float e = __expf(pre + pre);
            av = 1.f - __fdividef(2.f, e + 1.f);
        } else {
            av = __fdividef(1.f, 1.f + __expf(-pre));
        }
        act[tid] = av;
        __syncthreads();

        // --- replicated c/h update in ALL threads (identical fp32 per jj) ---
        float gi = act[jj], gf = act[64 + jj], gg = act[128 + jj], go = act[192 + jj];
        c = gf * c + gi * gg;
        float e = __expf(c + c);
        float th = 1.f - __fdividef(2.f, e + 1.f);
        float h = go * th;
        half h16 = __float2half_rn(h);

        if (q == 0) {
            out[obase + (size_t)t * H_] = h;           // exact fp32 h to output
            if (t < T_ - 1)
                hbuf[(t + 1) & 1][r * 64 + jj] = h16;  // local own slice
        } else if (t < T_ - 1) {
            // direct fire-and-forget send to peer's next buffer
            uint32_t dst = ((t & 1) == 0) ? raddr1 : raddr0;
            asm volatile("st.shared::cluster.u16 [%0], %1;"
                         :: "r"(dst), "h"(__half_as_ushort(h16)) : "memory");
            asm volatile("mbarrier.arrive.release.cluster.shared::cluster.b64 _, [%0];"
                         :: "r"(rmbar) : "memory");
        }
        __syncthreads();   // local h visible + act reusable

        xg_cur = xg_nx;
        xg_nx = xg_n2;
    }

    asm volatile("barrier.cluster.arrive.aligned;" ::: "memory");
    asm volatile("barrier.cluster.wait.aligned;" ::: "memory");
}

// ---------------------------------------------------------------------------
extern "C" void kernel_launch(void* const* d_in, const int* in_sizes, int n_in,
                              void* d_out, int out_size) {
    const float* x    = (const float*)d_in[0];
    const float* w_ih = (const float*)d_in[1];
    const float* w_hh = (const float*)d_in[2];
    const float* b_ih = (const float*)d_in[3];
    const float* b_hh = (const float*)d_in[4];
    float* out = (float*)d_out;

    bias_kernel<<<4, 256>>>(b_ih, b_hh);

    const int smem = 2 * 128 * ASTRIDE * (int)sizeof(half);  // 135168
    cudaFuncSetAttribute(gemm_kernel, cudaFuncAttributeMaxDynamicSharedMemorySize, smem);
    gemm_kernel<<<dim3(8, 512), 256, smem>>>(x, w_ih);

    lstm_kernel<<<128, 256>>>(w_hh, out);
}